// round 1
// baseline (speedup 1.0000x reference)
#include <cuda_runtime.h>
#include <math.h>

// Problem constants (match dataset: B=8, C=16, H=W=128, rate=2, stride=1, ksize=3)
#define NB 8
#define NC 16
#define HH 128
#define HD 64          // downsampled H/W
#define PN 4096        // number of patch positions (64*64)
#define KD 144         // 16*3*3 patch dim
#define VD 256         // 16*4*4 bg patch dim

// -------- scratch (device globals; no allocations allowed) --------
__device__ float g_fgp [(size_t)NB * PN * KD];   // 18.9 MB
__device__ float g_kern[(size_t)NB * PN * KD];   // 18.9 MB
__device__ float g_mm  [NB * PN];
__device__ float g_V   [(size_t)NB * PN * VD];   // 33.6 MB
__device__ float g_S   [(size_t)NB * PN * PN];   // 536.9 MB (scores -> attn in place)
__device__ float g_M   [(size_t)NB * PN * VD];   // 33.6 MB

// ============================================================================
// Prep: fgp / normalized kern / mm / V  — one block per (b, l)
// ============================================================================
__global__ void prep_kernel(const float* __restrict__ fg,
                            const float* __restrict__ bg,
                            const float* __restrict__ mask) {
    int l = blockIdx.x, b = blockIdx.y;
    int yl = l >> 6, xl = l & 63;
    int t = threadIdx.x;            // 256 threads

    // kern / fgp element for t < 144:  t = c*9 + i*3 + j, downsampled grid
    float kval = 0.f, fval = 0.f;
    if (t < KD) {
        int c = t / 9, rem = t % 9;
        int i = rem / 3, j = rem % 3;
        int y = yl - 1 + i, x = xl - 1 + j;
        if ((unsigned)y < (unsigned)HD && (unsigned)x < (unsigned)HD) {
            size_t base = (size_t)(b * NC + c) * (HH * HH);
            int off = (2 * y) * HH + 2 * x;      // ::2 downsample
            kval = bg[base + off];
            fval = fg[base + off];
        }
    }

    // block reduction of sum(kern^2)
    __shared__ float red[8];
    __shared__ float s_invn;
    float s = kval * kval;
    #pragma unroll
    for (int o = 16; o > 0; o >>= 1) s += __shfl_xor_sync(0xffffffffu, s, o);
    if ((t & 31) == 0) red[t >> 5] = s;
    __syncthreads();
    if (t == 0) {
        float tot = 0.f;
        #pragma unroll
        for (int w = 0; w < 8; w++) tot += red[w];
        s_invn = 1.f / fmaxf(sqrtf(tot), 1e-4f);   // NORM_EPS
    }
    __syncthreads();
    float invn = s_invn;

    if (t < KD) {
        size_t o = (size_t)(b * PN + l) * KD + t;
        g_kern[o] = kval * invn;
        g_fgp[o]  = fval;
    }

    // V: full-res 4x4 bg patch at (2*yl-1, 2*xl-1); t = c*16 + i*4 + j
    {
        int c = t >> 4, rem = t & 15;
        int i = rem >> 2, j = rem & 3;
        int y = 2 * yl - 1 + i, x = 2 * xl - 1 + j;
        float v = 0.f;
        if ((unsigned)y < (unsigned)HH && (unsigned)x < (unsigned)HH)
            v = bg[(size_t)(b * NC + c) * (HH * HH) + y * HH + x];
        g_V[(size_t)(b * PN + l) * VD + t] = v;
    }

    // mm: 1.0 if downsampled 3x3 mask patch sums to exactly 0
    if (t == 0) {
        float ms = 0.f;
        #pragma unroll
        for (int i = 0; i < 3; i++)
            #pragma unroll
            for (int j = 0; j < 3; j++) {
                int y = yl - 1 + i, x = xl - 1 + j;
                if ((unsigned)y < (unsigned)HD && (unsigned)x < (unsigned)HD)
                    ms += mask[(size_t)b * (HH * HH) + (2 * y) * HH + 2 * x];
            }
        g_mm[b * PN + l] = (ms == 0.f) ? 1.f : 0.f;
    }
}

// ============================================================================
// Scores GEMM (NT): S[p,l] = sum_k fgp[p,k] * kern[l,k]
// 128x128x16 tile, 8x8 microtile, 256 threads
// ============================================================================
__global__ void __launch_bounds__(256) score_gemm_kernel() {
    int b = blockIdx.z;
    const float* __restrict__ A  = g_fgp  + (size_t)b * PN * KD;
    const float* __restrict__ Bp = g_kern + (size_t)b * PN * KD;
    float* __restrict__ C = g_S + (size_t)b * PN * PN;
    int pm = blockIdx.y * 128, pn = blockIdx.x * 128;

    __shared__ float As[16][128];
    __shared__ float Bs[16][128];

    int tid = threadIdx.x;
    int tr = tid >> 4, tc = tid & 15;
    float acc[8][8] = {};

    for (int k0 = 0; k0 < KD; k0 += 16) {
        #pragma unroll
        for (int r = 0; r < 2; r++) {
            int f = tid + r * 256;
            int row = f >> 2, kk = (f & 3) * 4;
            float4 va = *(const float4*)(A  + (size_t)(pm + row) * KD + k0 + kk);
            As[kk + 0][row] = va.x; As[kk + 1][row] = va.y;
            As[kk + 2][row] = va.z; As[kk + 3][row] = va.w;
            float4 vb = *(const float4*)(Bp + (size_t)(pn + row) * KD + k0 + kk);
            Bs[kk + 0][row] = vb.x; Bs[kk + 1][row] = vb.y;
            Bs[kk + 2][row] = vb.z; Bs[kk + 3][row] = vb.w;
        }
        __syncthreads();
        #pragma unroll
        for (int k = 0; k < 16; k++) {
            float a[8], bb[8];
            #pragma unroll
            for (int i = 0; i < 8; i++) a[i]  = As[k][tr * 8 + i];
            #pragma unroll
            for (int j = 0; j < 8; j++) bb[j] = Bs[k][tc * 8 + j];
            #pragma unroll
            for (int i = 0; i < 8; i++)
                #pragma unroll
                for (int j = 0; j < 8; j++)
                    acc[i][j] += a[i] * bb[j];
        }
        __syncthreads();
    }

    #pragma unroll
    for (int i = 0; i < 8; i++) {
        float* cp = C + (size_t)(pm + tr * 8 + i) * PN + pn + tc * 8;
        *(float4*)(cp)     = make_float4(acc[i][0], acc[i][1], acc[i][2], acc[i][3]);
        *(float4*)(cp + 4) = make_float4(acc[i][4], acc[i][5], acc[i][6], acc[i][7]);
    }
}

// ============================================================================
// Softmax over l (row of 4096), in place: attn = softmax(10*s*mm) * mm
// One block (256 threads) per (b, p)
// ============================================================================
__global__ void __launch_bounds__(256) softmax_kernel() {
    int p = blockIdx.x, b = blockIdx.y;
    float* __restrict__ row = g_S + ((size_t)b * PN + p) * PN;
    const float* __restrict__ mm = g_mm + b * PN;
    int t = threadIdx.x;

    float zv[16];
    float zmax = -1e30f;
    #pragma unroll
    for (int r = 0; r < 16; r++) {
        int l = t + r * 256;
        float z = 10.f * row[l] * mm[l];
        zv[r] = z;
        zmax = fmaxf(zmax, z);
    }

    __shared__ float red[8];
    __shared__ float s_bc;
    #pragma unroll
    for (int o = 16; o > 0; o >>= 1) zmax = fmaxf(zmax, __shfl_xor_sync(0xffffffffu, zmax, o));
    if ((t & 31) == 0) red[t >> 5] = zmax;
    __syncthreads();
    if (t == 0) {
        float m = red[0];
        #pragma unroll
        for (int w = 1; w < 8; w++) m = fmaxf(m, red[w]);
        s_bc = m;
    }
    __syncthreads();
    float m = s_bc;

    float lsum = 0.f;
    #pragma unroll
    for (int r = 0; r < 16; r++) {
        float e = __expf(zv[r] - m);
        zv[r] = e;
        lsum += e;
    }
    #pragma unroll
    for (int o = 16; o > 0; o >>= 1) lsum += __shfl_xor_sync(0xffffffffu, lsum, o);
    __syncthreads();
    if ((t & 31) == 0) red[t >> 5] = lsum;
    __syncthreads();
    if (t == 0) {
        float tot = 0.f;
        #pragma unroll
        for (int w = 0; w < 8; w++) tot += red[w];
        s_bc = 1.f / tot;
    }
    __syncthreads();
    float inv = s_bc;

    #pragma unroll
    for (int r = 0; r < 16; r++) {
        int l = t + r * 256;
        row[l] = zv[r] * inv * mm[l];
    }
}

// ============================================================================
// Recon GEMM (NN): M[p,r] = sum_l attn[p,l] * V[l,r]   (N=256, K=4096)
// ============================================================================
__global__ void __launch_bounds__(256) recon_gemm_kernel() {
    int b = blockIdx.z;
    const float* __restrict__ A  = g_S + (size_t)b * PN * PN;   // attn [P, L]
    const float* __restrict__ Bp = g_V + (size_t)b * PN * VD;   // [L, 256]
    float* __restrict__ C = g_M + (size_t)b * PN * VD;
    int pm = blockIdx.y * 128, pn = blockIdx.x * 128;

    __shared__ float As[16][128];
    __shared__ float Bs[16][128];

    int tid = threadIdx.x;
    int tr = tid >> 4, tc = tid & 15;
    float acc[8][8] = {};

    for (int k0 = 0; k0 < PN; k0 += 16) {
        #pragma unroll
        for (int r = 0; r < 2; r++) {
            int f = tid + r * 256;
            int row = f >> 2, kk = (f & 3) * 4;
            float4 va = *(const float4*)(A + (size_t)(pm + row) * PN + k0 + kk);
            As[kk + 0][row] = va.x; As[kk + 1][row] = va.y;
            As[kk + 2][row] = va.z; As[kk + 3][row] = va.w;
            int kb = f >> 5, nb = (f & 31) * 4;
            float4 vb = *(const float4*)(Bp + (size_t)(k0 + kb) * VD + pn + nb);
            *(float4*)&Bs[kb][nb] = vb;
        }
        __syncthreads();
        #pragma unroll
        for (int k = 0; k < 16; k++) {
            float a[8], bb[8];
            #pragma unroll
            for (int i = 0; i < 8; i++) a[i]  = As[k][tr * 8 + i];
            #pragma unroll
            for (int j = 0; j < 8; j++) bb[j] = Bs[k][tc * 8 + j];
            #pragma unroll
            for (int i = 0; i < 8; i++)
                #pragma unroll
                for (int j = 0; j < 8; j++)
                    acc[i][j] += a[i] * bb[j];
        }
        __syncthreads();
    }

    #pragma unroll
    for (int i = 0; i < 8; i++) {
        float* cp = C + (size_t)(pm + tr * 8 + i) * VD + pn + tc * 8;
        *(float4*)(cp)     = make_float4(acc[i][0], acc[i][1], acc[i][2], acc[i][3]);
        *(float4*)(cp + 4) = make_float4(acc[i][4], acc[i][5], acc[i][6], acc[i][7]);
    }
}

// ============================================================================
// Overlap-add gather: out[b,c,u,v] = 0.25 * sum over <=4 (y,x) of M[...]
// scatter positions: out[2y-1+i, 2x-1+j] += attn-weighted patch, i,j in [0,4)
// ============================================================================
__global__ void gather_kernel(float* __restrict__ out) {
    int idx = blockIdx.x * blockDim.x + threadIdx.x;
    if (idx >= NB * NC * HH * HH) return;
    int v = idx & 127;
    int u = (idx >> 7) & 127;
    int c = (idx >> 14) & 15;
    int b = idx >> 18;

    int yh = (u + 1) >> 1;
    int xh = (v + 1) >> 1;
    float acc = 0.f;
    #pragma unroll
    for (int dy = 0; dy < 2; dy++) {
        int y = yh - dy;
        if ((unsigned)y >= (unsigned)HD) continue;
        int i = u + 1 - 2 * y;      // in [0,4)
        #pragma unroll
        for (int dx = 0; dx < 2; dx++) {
            int x = xh - dx;
            if ((unsigned)x >= (unsigned)HD) continue;
            int j = v + 1 - 2 * x;  // in [0,4)
            acc += g_M[((size_t)(b * PN + y * 64 + x)) * VD + c * 16 + i * 4 + j];
        }
    }
    out[idx] = 0.25f * acc;
}

// ============================================================================
extern "C" void kernel_launch(void* const* d_in, const int* in_sizes, int n_in,
                              void* d_out, int out_size) {
    const float* fg   = (const float*)d_in[0];
    const float* bg   = (const float*)d_in[1];
    const float* mask = (const float*)d_in[2];
    float* out = (float*)d_out;

    prep_kernel<<<dim3(PN, NB), 256>>>(fg, bg, mask);
    score_gemm_kernel<<<dim3(PN / 128, PN / 128, NB), 256>>>();
    softmax_kernel<<<dim3(PN, NB), 256>>>();
    recon_gemm_kernel<<<dim3(VD / 128, PN / 128, NB), 256>>>();
    int total = NB * NC * HH * HH;
    gather_kernel<<<(total + 255) / 256, 256>>>(out);
}